// round 9
// baseline (speedup 1.0000x reference)
#include <cuda_runtime.h>
#include <cstdint>

#define S_LEN 128
#define B_SZ  32
#define H_DIM 512
#define V_SZ  10000

typedef unsigned long long u64;

// ---------------- scratch (device globals; no allocation allowed) ----------------
__device__ float g_X[S_LEN * B_SZ * H_DIM];       // layer input / tops (8 MB)
__device__ float g_Y[S_LEN * B_SZ * H_DIM];       // layer-0 outputs (8 MB)
__device__ float g_A[S_LEN * B_SZ * 3 * H_DIM];   // precomputed x@Wx+bx (24 MB)
__device__ float g_h[B_SZ * H_DIM];               // h  [b][k]
__device__ float g_rh[B_SZ * H_DIM];              // r*h [b][k]
__device__ int   g_is64;

// Flag barrier: one 128-B line (32 u32 slots) per (bg, group). Monotone counters,
// never reset -> replay/graph safe. Zero-initialized at module load.
__device__ __align__(128) unsigned g_slots[4][2][32];

// ---------------- token dtype detector ----------------
__global__ void detect_kernel(const int* __restrict__ t32) {
    if (threadIdx.x == 0 && blockIdx.x == 0) {
        unsigned o = 0;
        for (int i = 0; i < 128; i++) o |= (unsigned)t32[2 * i + 1];
        g_is64 = (o == 0) ? 1 : 0;
    }
}

// ---------------- embedding gather (dtype-robust, clamped) ----------------
__global__ void embed_kernel(const void* __restrict__ tok,
                             const float* __restrict__ emb,
                             float* __restrict__ X) {
    int row = blockIdx.x;
    long long t;
    if (g_is64) t = ((const long long*)tok)[row];
    else        t = (long long)((const int*)tok)[row];
    if (t < 0) t = 0;
    if (t >= V_SZ) t = V_SZ - 1;
    const float4* src = (const float4*)(emb + (size_t)t * H_DIM);
    float4* dst = (float4*)(X + (size_t)row * H_DIM);
    for (int i = threadIdx.x; i < H_DIM / 4; i += blockDim.x) dst[i] = src[i];
}

// ---------------- tf32 mma + cp.async helpers ----------------
#define BM 128
#define BN 128
#define BKK 16
#define AST 20
#define BST_KN 136
#define BST_NK 20

__device__ __forceinline__ unsigned f2tf(float x) {
    unsigned r; asm("cvt.rna.tf32.f32 %0, %1;" : "=r"(r) : "f"(x)); return r;
}
__device__ __forceinline__ void mma8(float* c, const unsigned* a, const unsigned* b) {
    asm volatile(
        "mma.sync.aligned.m16n8k8.row.col.f32.tf32.tf32.f32 "
        "{%0,%1,%2,%3}, {%4,%5,%6,%7}, {%8,%9}, {%0,%1,%2,%3};\n"
        : "+f"(c[0]), "+f"(c[1]), "+f"(c[2]), "+f"(c[3])
        : "r"(a[0]), "r"(a[1]), "r"(a[2]), "r"(a[3]), "r"(b[0]), "r"(b[1]));
}
__device__ __forceinline__ void cpa16(unsigned dst, const void* src, bool pred) {
    int sz = pred ? 16 : 0;
    asm volatile("cp.async.cg.shared.global [%0], [%1], 16, %2;\n"
                 :: "r"(dst), "l"(src), "r"(sz));
}
__device__ __forceinline__ void cpa_commit() {
    asm volatile("cp.async.commit_group;\n" ::: "memory");
}
__device__ __forceinline__ void cpa_wait1() {
    asm volatile("cp.async.wait_group 1;\n" ::: "memory");
}
__device__ __forceinline__ unsigned smem_u32(const void* p) {
    return (unsigned)__cvta_generic_to_shared(p);
}
__device__ __forceinline__ void fma2(u64& acc, u64 a, u64 b) {
    asm("fma.rn.f32x2 %0, %1, %2, %0;" : "+l"(acc) : "l"(a), "l"(b));
}
__device__ __forceinline__ float acc_sum(u64 a) {
    unsigned lo, hi;
    asm("mov.b64 {%0,%1}, %2;" : "=r"(lo), "=r"(hi) : "l"(a));
    return __uint_as_float(lo) + __uint_as_float(hi);
}
__device__ __forceinline__ void named_bar(int id) {
    asm volatile("bar.sync %0, %1;" :: "r"(id), "r"(128) : "memory");
}

// Atomic-free group barrier: arrival = flag store; wait = warp-0 polls full line.
__device__ __forceinline__ void group_barrier(unsigned* slotline, int og,
                                              unsigned target, int gtid, int nb) {
    named_bar(nb);                       // group execution + cta-mem sync
    if (gtid < 32) {
        if (gtid == 0) { __threadfence(); __stcg(&slotline[og], target); }
        unsigned it = 0;
        while (true) {
            unsigned v = __ldcg(&slotline[gtid]);
            if (__all_sync(0xffffffffu, v >= target)) break;
            if (++it > 20000u) __nanosleep(64);
            if (it > 400000u) break;     // safety valve: never hang the container
        }
        __threadfence();
    }
    named_bar(nb);
}

// ---------- fused 3-gate input GEMM (2-stage cp.async) --------------------------
__global__ __launch_bounds__(256, 2)
void gemm_ax(const float* __restrict__ A,          // X [M,512]
             const float* __restrict__ Wxl,        // [3,512,512]
             const float* __restrict__ bxl,        // [3,512]
             float* __restrict__ C) {              // [M,1536]
    __shared__ float As[2][BM * AST];
    __shared__ float Bs[2][BKK * BST_KN];

    int tid = threadIdx.x;
    int lane = tid & 31, warp = tid >> 5;
    int wr = warp >> 2, wc = warp & 3;
    int m0 = blockIdx.y * BM, n0 = blockIdx.x * BN;
    int g = n0 >> 9, col0 = n0 & 511;
    const float* Bg = Wxl + (size_t)g * H_DIM * H_DIM;

    const int ra = tid >> 1, ha = tid & 1;
    const int krb = tid >> 4, csb = tid & 15;
    const float* Asrc = A + (size_t)(m0 + ra) * H_DIM + ha * 8;
    const float* Bsrc = Bg + (size_t)krb * H_DIM + col0 + csb * 8;

    float c[4][4][4];
    #pragma unroll
    for (int i = 0; i < 4; i++)
        #pragma unroll
        for (int j = 0; j < 4; j++)
            #pragma unroll
            for (int k = 0; k < 4; k++) c[i][j][k] = 0.f;

    const int NK = H_DIM / BKK;
    {
        unsigned da0 = smem_u32(&As[0][ra * AST + ha * 8]);
        cpa16(da0, Asrc, true); cpa16(da0 + 16, Asrc + 4, true);
        unsigned db0 = smem_u32(&Bs[0][krb * BST_KN + csb * 8]);
        cpa16(db0, Bsrc, true); cpa16(db0 + 16, Bsrc + 4, true);
        cpa_commit();
    }

    for (int it = 0; it < NK; it++) {
        if (it + 1 < NK) {
            int kk = (it + 1) * BKK, buf = (it + 1) & 1;
            unsigned da = smem_u32(&As[buf][ra * AST + ha * 8]);
            cpa16(da, Asrc + kk, true); cpa16(da + 16, Asrc + kk + 4, true);
            unsigned db = smem_u32(&Bs[buf][krb * BST_KN + csb * 8]);
            cpa16(db, Bsrc + (size_t)kk * H_DIM, true);
            cpa16(db + 16, Bsrc + (size_t)kk * H_DIM + 4, true);
        }
        cpa_commit();
        cpa_wait1();
        __syncthreads();

        const float* Ab = As[it & 1];
        const float* Bb = Bs[it & 1];
        int ar = lane >> 2, ak = lane & 3;
        #pragma unroll
        for (int kq = 0; kq < BKK; kq += 8) {
            unsigned af[4][4], bf[4][2];
            #pragma unroll
            for (int mt = 0; mt < 4; mt++) {
                int rb = wr * 64 + mt * 16;
                af[mt][0] = f2tf(Ab[(rb + ar)     * AST + kq + ak]);
                af[mt][1] = f2tf(Ab[(rb + ar + 8) * AST + kq + ak]);
                af[mt][2] = f2tf(Ab[(rb + ar)     * AST + kq + ak + 4]);
                af[mt][3] = f2tf(Ab[(rb + ar + 8) * AST + kq + ak + 4]);
            }
            #pragma unroll
            for (int nt = 0; nt < 4; nt++) {
                int cb = wc * 32 + nt * 8 + (lane >> 2);
                bf[nt][0] = f2tf(Bb[(kq + ak)     * BST_KN + cb]);
                bf[nt][1] = f2tf(Bb[(kq + ak + 4) * BST_KN + cb]);
            }
            #pragma unroll
            for (int mt = 0; mt < 4; mt++)
                #pragma unroll
                for (int nt = 0; nt < 4; nt++)
                    mma8(c[mt][nt], af[mt], bf[nt]);
        }
        __syncthreads();
    }

    #pragma unroll
    for (int mt = 0; mt < 4; mt++) {
        #pragma unroll
        for (int nt = 0; nt < 4; nt++) {
            int r0 = m0 + wr * 64 + mt * 16 + (lane >> 2);
            int cc = n0 + wc * 32 + nt * 8 + (lane & 3) * 2;
            float bv0 = bxl[g * H_DIM + (cc & 511)];
            float bv1 = bxl[g * H_DIM + ((cc + 1) & 511)];
            C[(size_t)r0 * 1536 + cc]           = c[mt][nt][0] + bv0;
            C[(size_t)r0 * 1536 + cc + 1]       = c[mt][nt][1] + bv1;
            C[(size_t)(r0 + 8) * 1536 + cc]     = c[mt][nt][2] + bv0;
            C[(size_t)(r0 + 8) * 1536 + cc + 1] = c[mt][nt][3] + bv1;
        }
    }
}

// ---------------- logits GEMM, 3-stage cp.async pipeline ------------------------
#define GBUF 2560
__global__ __launch_bounds__(256, 2)
void gemm_bt(const float* __restrict__ A,
             const float* __restrict__ Bm,
             const float* __restrict__ bias,
             float* __restrict__ C, int N) {
    extern __shared__ float sm[];
    float* AsB = sm;              // 3 * 2560
    float* BsB = sm + 3 * GBUF;   // 3 * 2560

    int tid = threadIdx.x;
    int lane = tid & 31, warp = tid >> 5;
    int wr = warp >> 2, wc = warp & 3;
    int m0 = blockIdx.y * BM, n0 = blockIdx.x * BN;

    const int ra = tid >> 1, ha = tid & 1;
    const int gn = n0 + ra;
    const bool bok = (gn < N);
    const float* Asrc = A + (size_t)(m0 + ra) * H_DIM + ha * 8;
    const float* Bsrc = Bm + (size_t)(bok ? gn : 0) * H_DIM + ha * 8;

    float c[4][4][4];
    #pragma unroll
    for (int i = 0; i < 4; i++)
        #pragma unroll
        for (int j = 0; j < 4; j++)
            #pragma unroll
            for (int k = 0; k < 4; k++) c[i][j][k] = 0.f;

    const int NK = H_DIM / BKK;   // 32
    #pragma unroll
    for (int s = 0; s < 2; s++) {
        int kk = s * BKK;
        unsigned da = smem_u32(&AsB[s * GBUF + ra * AST + ha * 8]);
        cpa16(da, Asrc + kk, true); cpa16(da + 16, Asrc + kk + 4, true);
        unsigned db = smem_u32(&BsB[s * GBUF + ra * BST_NK + ha * 8]);
        cpa16(db, Bsrc + kk, bok); cpa16(db + 16, Bsrc + kk + 4, bok);
        cpa_commit();
    }

    int buf = 0;
    for (int it = 0; it < NK; it++) {
        cpa_wait1();
        __syncthreads();

        const float* Ab = &AsB[buf * GBUF];
        const float* Bb = &BsB[buf * GBUF];
        int ar = lane >> 2, ak = lane & 3;
        #pragma unroll
        for (int kq = 0; kq < BKK; kq += 8) {
            unsigned af[4][4], bf[4][2];
            #pragma unroll
            for (int mt = 0; mt < 4; mt++) {
                int rb = wr * 64 + mt * 16;
                af[mt][0] = f2tf(Ab[(rb + ar)     * AST + kq + ak]);
                af[mt][1] = f2tf(Ab[(rb + ar + 8) * AST + kq + ak]);
                af[mt][2] = f2tf(Ab[(rb + ar)     * AST + kq + ak + 4]);
                af[mt][3] = f2tf(Ab[(rb + ar + 8) * AST + kq + ak + 4]);
            }
            #pragma unroll
            for (int nt = 0; nt < 4; nt++) {
                int cb = wc * 32 + nt * 8 + (lane >> 2);
                bf[nt][0] = f2tf(Bb[cb * BST_NK + kq + ak]);
                bf[nt][1] = f2tf(Bb[cb * BST_NK + kq + ak + 4]);
            }
            #pragma unroll
            for (int mt = 0; mt < 4; mt++)
                #pragma unroll
                for (int nt = 0; nt < 4; nt++)
                    mma8(c[mt][nt], af[mt], bf[nt]);
        }
        __syncthreads();

        if (it + 2 < NK) {
            int kk = (it + 2) * BKK;
            int nb = (it + 2) % 3;     // stage s lives in slot s%3
            unsigned da = smem_u32(&AsB[nb * GBUF + ra * AST + ha * 8]);
            cpa16(da, Asrc + kk, true); cpa16(da + 16, Asrc + kk + 4, true);
            unsigned db = smem_u32(&BsB[nb * GBUF + ra * BST_NK + ha * 8]);
            cpa16(db, Bsrc + kk, bok); cpa16(db + 16, Bsrc + kk + 4, bok);
        }
        cpa_commit();
        buf = (buf + 1) % 3;
    }

    #pragma unroll
    for (int mt = 0; mt < 4; mt++) {
        #pragma unroll
        for (int nt = 0; nt < 4; nt++) {
            int r0 = m0 + wr * 64 + mt * 16 + (lane >> 2);
            int cc = n0 + wc * 32 + nt * 8 + (lane & 3) * 2;
            if (cc < N) {
                float bv = bias[cc];
                C[(size_t)r0 * N + cc]       = c[mt][nt][0] + bv;
                C[(size_t)(r0 + 8) * N + cc] = c[mt][nt][2] + bv;
            }
            if (cc + 1 < N) {
                float bv = bias[cc + 1];
                C[(size_t)r0 * N + cc + 1]       = c[mt][nt][1] + bv;
                C[(size_t)(r0 + 8) * N + cc + 1] = c[mt][nt][3] + bv;
            }
        }
    }
}

// ---------------- persistent GRU recurrence (one layer, 128 CTAs) ----------------
// CTA = (bg 0..3, og 0..31): 16 o's, 8 batches. Threads split into 2 independent
// 128-thread groups (batches 0-3 / 4-7 of the bg), each with its own flag barrier
// -> one group's barrier wait overlaps the other's compute on the same SM.
#define HSS 516
#define RST 20
__global__ __launch_bounds__(256)
void recur_kernel(const float* __restrict__ A, const float* __restrict__ U,
                  const float* __restrict__ h0, float* __restrict__ Y,
                  float* __restrict__ h_final) {
    extern __shared__ float smem[];
    float* Urz   = smem;                    // 32*516 (rows 0-15: r, 16-31: z)
    float* Uc    = Urz + 32 * HSS;          // 16*516
    float* hS    = Uc + 16 * HSS;           // 2 groups * 4 b * 516
    float* redS  = hS + 8 * HSS;            // 2 * 32 * 20
    float* zS    = redS + 2 * 32 * RST;     // 2 * 64
    float* holdS = zS + 128;                // 2 * 64
    __shared__ unsigned baseS[2];

    const int tid = threadIdx.x, lane = tid & 31;
    const int g2 = tid >> 7, gtid = tid & 127;
    const int q = (tid >> 5) & 3;                 // k-quarter (warp within group)
    const int slot = lane >> 2, bl = lane & 3;
    const int og = blockIdx.x & 31, bg = blockIdx.x >> 5;
    const int prow = gtid >> 2, pb = gtid & 3;
    const int bglob = bg * 8 + g2 * 4 + pb;       // finalize-role batch
    const int nb = 1 + g2;                        // named barrier id

    float* hSg    = hS + g2 * 4 * HSS;
    float* redSg  = redS + g2 * 32 * RST;
    float* zSg    = zS + g2 * 64;
    float* holdSg = holdS + g2 * 64;
    unsigned* slotline = &g_slots[bg][g2][0];

    // ---- stage transposed U (once, whole CTA)
    for (int idx = tid; idx < 2048; idx += 256) {
        int i = idx >> 2, o4 = idx & 3;
        float4 v0 = *(const float4*)(U + (size_t)i * H_DIM + og * 16 + o4 * 4);
        float4 v1 = *(const float4*)(U + (size_t)H_DIM * H_DIM + (size_t)i * H_DIM + og * 16 + o4 * 4);
        float4 v2 = *(const float4*)(U + (size_t)2 * H_DIM * H_DIM + (size_t)i * H_DIM + og * 16 + o4 * 4);
        Urz[(o4 * 4 + 0) * HSS + i] = v0.x; Urz[(o4 * 4 + 1) * HSS + i] = v0.y;
        Urz[(o4 * 4 + 2) * HSS + i] = v0.z; Urz[(o4 * 4 + 3) * HSS + i] = v0.w;
        Urz[(16 + o4 * 4 + 0) * HSS + i] = v1.x; Urz[(16 + o4 * 4 + 1) * HSS + i] = v1.y;
        Urz[(16 + o4 * 4 + 2) * HSS + i] = v1.z; Urz[(16 + o4 * 4 + 3) * HSS + i] = v1.w;
        Uc[(o4 * 4 + 0) * HSS + i] = v2.x; Uc[(o4 * 4 + 1) * HSS + i] = v2.y;
        Uc[(o4 * 4 + 2) * HSS + i] = v2.z; Uc[(o4 * 4 + 3) * HSS + i] = v2.w;
    }

    // ---- seed g_h (og==0 CTA; each group seeds its 4 batches)
    if (og == 0) {
        for (int i = gtid; i < 512; i += 128) {
            int b = i >> 7, kq = i & 127;
            float4 v = *(const float4*)(h0 + (size_t)(bg * 8 + g2 * 4 + b) * H_DIM + kq * 4);
            __stcg((float4*)(g_h + (size_t)(bg * 8 + g2 * 4 + b) * H_DIM + kq * 4), v);
        }
    }

    // ---- read barrier base (slots all equal at kernel entry)
    if (gtid == 0) baseS[g2] = __ldcg(&slotline[og]);
    __syncthreads();                  // U staged + base ready; groups diverge after
    const unsigned base = baseS[g2];

    group_barrier(slotline, og, base + 1, gtid, nb);   // h seeded everywhere

    float hn_last = 0.f;

    for (int t = 0; t < S_LEN; ++t) {
        // prefetch A operands for finalize roles
        float av1 = __ldg(&A[(size_t)(t * B_SZ + bglob) * 1536 +
                             (prow < 16 ? 0 : 512) + og * 16 + (prow & 15)]);
        float av2 = (gtid < 64)
            ? __ldg(&A[(size_t)(t * B_SZ + bglob) * 1536 + 1024 + og * 16 + prow])
            : 0.f;

        // ---- stage this group's 4 batches of h
        for (int i = gtid; i < 512; i += 128) {
            int b = i >> 7, kq = i & 127;
            float4 v = __ldcg((const float4*)(g_h + (size_t)(bg * 8 + g2 * 4 + b) * H_DIM + kq * 4));
            *(float4*)&hSg[b * HSS + kq * 4] = v;
        }
        named_bar(nb);

        // ---- phase 1 compute: rows slot+8j (j=0..3: r0-15,z0-15), k-quarter q
        {
            const float* hb = hSg + bl * HSS + q * 128;
            const float* ub = Urz + slot * HSS + q * 128;
            u64 a0 = 0ull, a1 = 0ull, a2 = 0ull, a3 = 0ull;
            #pragma unroll 4
            for (int c = 0; c < 32; c++) {
                ulonglong2 hv = *(const ulonglong2*)(hb + c * 4);
                ulonglong2 u0 = *(const ulonglong2*)(ub + c * 4);
                ulonglong2 u1 = *(const ulonglong2*)(ub + 8 * HSS + c * 4);
                ulonglong2 u2 = *(const ulonglong2*)(ub + 16 * HSS + c * 4);
                ulonglong2 u3 = *(const ulonglong2*)(ub + 24 * HSS + c * 4);
                fma2(a0, hv.x, u0.x); fma2(a1, hv.x, u1.x);
                fma2(a2, hv.x, u2.x); fma2(a3, hv.x, u3.x);
                fma2(a0, hv.y, u0.y); fma2(a1, hv.y, u1.y);
                fma2(a2, hv.y, u2.y); fma2(a3, hv.y, u3.y);
            }
            redSg[(slot +  0) * RST + bl * 4 + q] = acc_sum(a0);
            redSg[(slot +  8) * RST + bl * 4 + q] = acc_sum(a1);
            redSg[(slot + 16) * RST + bl * 4 + q] = acc_sum(a2);
            redSg[(slot + 24) * RST + bl * 4 + q] = acc_sum(a3);
        }
        named_bar(nb);

        // ---- phase 1 finalize: row = prow (0-15 r, 16-31 z), batch = pb
        {
            float4 p = *(const float4*)&redSg[prow * RST + pb * 4];
            float sum = (p.x + p.y) + (p.z + p.w) + av1;
            float sg = 1.f / (1.f + __expf(-sum));
            if (prow < 16) {
                int o = og * 16 + prow;
                float hold = hSg[pb * HSS + o];
                holdSg[prow * 4 + pb] = hold;
                __stcg(&g_rh[(size_t)bglob * H_DIM + o], sg * hold);
            } else {
                zSg[(prow - 16) * 4 + pb] = sg;
            }
        }
        group_barrier(slotline, og, base + 2 + 2 * t, gtid, nb);

        // ---- stage this group's 4 batches of rh
        for (int i = gtid; i < 512; i += 128) {
            int b = i >> 7, kq = i & 127;
            float4 v = __ldcg((const float4*)(g_rh + (size_t)(bg * 8 + g2 * 4 + b) * H_DIM + kq * 4));
            *(float4*)&hSg[b * HSS + kq * 4] = v;
        }
        named_bar(nb);

        // ---- phase 2 compute: rows slot, slot+8 (candidate), k-quarter q
        {
            const float* hb = hSg + bl * HSS + q * 128;
            const float* ub = Uc + slot * HSS + q * 128;
            u64 a0 = 0ull, a1 = 0ull;
            #pragma unroll 4
            for (int c = 0; c < 32; c++) {
                ulonglong2 hv = *(const ulonglong2*)(hb + c * 4);
                ulonglong2 u0 = *(const ulonglong2*)(ub + c * 4);
                ulonglong2 u1 = *(const ulonglong2*)(ub + 8 * HSS + c * 4);
                fma2(a0, hv.x, u0.x); fma2(a1, hv.x, u1.x);
                fma2(a0, hv.y, u0.y); fma2(a1, hv.y, u1.y);
            }
            redSg[(slot + 0) * RST + bl * 4 + q] = acc_sum(a0);
            redSg[(slot + 8) * RST + bl * 4 + q] = acc_sum(a1);
        }
        named_bar(nb);

        // ---- phase 2 finalize (64 threads/group): row = prow (0-15), batch = pb
        if (gtid < 64) {
            float4 p = *(const float4*)&redSg[prow * RST + pb * 4];
            float hh = tanhf((p.x + p.y) + (p.z + p.w) + av2);
            float z = zSg[prow * 4 + pb];
            float hold = holdSg[prow * 4 + pb];
            float hn = fmaf(z, hh - hold, hold);
            hn_last = hn;
            int o = og * 16 + prow;
            __stcg(&g_h[(size_t)bglob * H_DIM + o], hn);
            __stcg(&Y[(size_t)(t * B_SZ + bglob) * H_DIM + o], hn);
        }
        group_barrier(slotline, og, base + 3 + 2 * t, gtid, nb);
    }

    if (gtid < 64)
        h_final[(size_t)bglob * H_DIM + og * 16 + prow] = hn_last;
}

// ---------------- launch ----------------
extern "C" void kernel_launch(void* const* d_in, const int* in_sizes, int n_in,
                              void* d_out, int out_size) {
    const void*  tokens = d_in[0];
    const float* h0  = (const float*)d_in[1];
    const float* emb = (const float*)d_in[2];
    const float* Wx  = (const float*)d_in[3];
    const float* bx  = (const float*)d_in[4];
    const float* U   = (const float*)d_in[5];
    const float* Wy  = (const float*)d_in[6];
    const float* by  = (const float*)d_in[7];

    float* logits = (float*)d_out;                              // [S,B,V]
    float* hfin   = logits + (size_t)S_LEN * B_SZ * V_SZ;       // [L,B,H]

    float *dX, *dY, *dA;
    cudaGetSymbolAddress((void**)&dX, g_X);
    cudaGetSymbolAddress((void**)&dY, g_Y);
    cudaGetSymbolAddress((void**)&dA, g_A);

    const int M = S_LEN * B_SZ;
    const int RSMEM = (32 * HSS + 16 * HSS + 8 * HSS + 2 * 32 * RST + 128 + 128) * 4;
    cudaFuncSetAttribute(recur_kernel, cudaFuncAttributeMaxDynamicSharedMemorySize, RSMEM);
    const int GSMEM = 6 * GBUF * 4;   // 61440
    cudaFuncSetAttribute(gemm_bt, cudaFuncAttributeMaxDynamicSharedMemorySize, GSMEM);

    dim3 blk(256);

    detect_kernel<<<1, 32>>>((const int*)tokens);
    embed_kernel<<<M, 128>>>(tokens, emb, dX);

    gemm_ax<<<dim3(12, M / 128), blk>>>(dX, Wx, bx, dA);

    recur_kernel<<<128, 256, RSMEM>>>(dA, U, h0, dY, hfin);

    gemm_ax<<<dim3(12, M / 128), blk>>>(dY, Wx + (size_t)3 * H_DIM * H_DIM,
                                        bx + 3 * H_DIM, dA);

    recur_kernel<<<128, 256, RSMEM>>>(dA, U + (size_t)3 * H_DIM * H_DIM,
                                      h0 + B_SZ * H_DIM, dX, hfin + B_SZ * H_DIM);

    gemm_bt<<<dim3((V_SZ + 127) / 128, M / 128), blk, GSMEM>>>(dX, Wy, by, logits, V_SZ);
}

// round 10
// speedup vs baseline: 1.1503x; 1.1503x over previous
#include <cuda_runtime.h>
#include <cstdint>

#define S_LEN 128
#define B_SZ  32
#define H_DIM 512
#define V_SZ  10000

typedef unsigned long long u64;

// ---------------- scratch (device globals; no allocation allowed) ----------------
__device__ float g_X[S_LEN * B_SZ * H_DIM];       // layer input / tops (8 MB)
__device__ float g_Y[S_LEN * B_SZ * H_DIM];       // layer-0 outputs (8 MB)
__device__ float g_A[S_LEN * B_SZ * 3 * H_DIM];   // precomputed x@Wx+bx (24 MB)
__device__ float g_h[B_SZ * H_DIM];               // h  [b][k]
__device__ float g_rh[B_SZ * H_DIM];              // r*h [b][k]
__device__ int   g_is64;

// ---------------- token dtype detector ----------------
__global__ void detect_kernel(const int* __restrict__ t32) {
    if (threadIdx.x == 0 && blockIdx.x == 0) {
        unsigned o = 0;
        for (int i = 0; i < 128; i++) o |= (unsigned)t32[2 * i + 1];
        g_is64 = (o == 0) ? 1 : 0;
    }
}

// ---------------- embedding gather (dtype-robust, clamped) ----------------
__global__ void embed_kernel(const void* __restrict__ tok,
                             const float* __restrict__ emb,
                             float* __restrict__ X) {
    int row = blockIdx.x;
    long long t;
    if (g_is64) t = ((const long long*)tok)[row];
    else        t = (long long)((const int*)tok)[row];
    if (t < 0) t = 0;
    if (t >= V_SZ) t = V_SZ - 1;
    const float4* src = (const float4*)(emb + (size_t)t * H_DIM);
    float4* dst = (float4*)(X + (size_t)row * H_DIM);
    for (int i = threadIdx.x; i < H_DIM / 4; i += blockDim.x) dst[i] = src[i];
}

// ---------------- tf32 mma + cp.async helpers ----------------
#define BM 128
#define BN 128
#define BKK 16
#define AST 20
#define BST_KN 136
#define BST_NK 20

__device__ __forceinline__ unsigned f2tf(float x) {
    unsigned r; asm("cvt.rna.tf32.f32 %0, %1;" : "=r"(r) : "f"(x)); return r;
}
__device__ __forceinline__ void mma8(float* c, const unsigned* a, const unsigned* b) {
    asm volatile(
        "mma.sync.aligned.m16n8k8.row.col.f32.tf32.tf32.f32 "
        "{%0,%1,%2,%3}, {%4,%5,%6,%7}, {%8,%9}, {%0,%1,%2,%3};\n"
        : "+f"(c[0]), "+f"(c[1]), "+f"(c[2]), "+f"(c[3])
        : "r"(a[0]), "r"(a[1]), "r"(a[2]), "r"(a[3]), "r"(b[0]), "r"(b[1]));
}
__device__ __forceinline__ void cpa16(unsigned dst, const void* src, bool pred) {
    int sz = pred ? 16 : 0;
    asm volatile("cp.async.cg.shared.global [%0], [%1], 16, %2;\n"
                 :: "r"(dst), "l"(src), "r"(sz));
}
__device__ __forceinline__ void cpa_commit() {
    asm volatile("cp.async.commit_group;\n" ::: "memory");
}
__device__ __forceinline__ void cpa_wait1() {
    asm volatile("cp.async.wait_group 1;\n" ::: "memory");
}
__device__ __forceinline__ unsigned smem_u32(const void* p) {
    return (unsigned)__cvta_generic_to_shared(p);
}
__device__ __forceinline__ void fma2(u64& acc, u64 a, u64 b) {
    asm("fma.rn.f32x2 %0, %1, %2, %0;" : "+l"(acc) : "l"(a), "l"(b));
}
__device__ __forceinline__ float acc_sum(u64 a) {
    unsigned lo, hi;
    asm("mov.b64 {%0,%1}, %2;" : "=r"(lo), "=r"(hi) : "l"(a));
    return __uint_as_float(lo) + __uint_as_float(hi);
}
__device__ __forceinline__ void cluster_sync() {
    asm volatile("barrier.cluster.arrive.aligned;" ::: "memory");
    asm volatile("barrier.cluster.wait.aligned;" ::: "memory");
}

// ---------- fused 3-gate input GEMM (2-stage cp.async) --------------------------
__global__ __launch_bounds__(256, 2)
void gemm_ax(const float* __restrict__ A,          // X [M,512]
             const float* __restrict__ Wxl,        // [3,512,512]
             const float* __restrict__ bxl,        // [3,512]
             float* __restrict__ C) {              // [M,1536]
    __shared__ float As[2][BM * AST];
    __shared__ float Bs[2][BKK * BST_KN];

    int tid = threadIdx.x;
    int lane = tid & 31, warp = tid >> 5;
    int wr = warp >> 2, wc = warp & 3;
    int m0 = blockIdx.y * BM, n0 = blockIdx.x * BN;
    int g = n0 >> 9, col0 = n0 & 511;
    const float* Bg = Wxl + (size_t)g * H_DIM * H_DIM;

    const int ra = tid >> 1, ha = tid & 1;
    const int krb = tid >> 4, csb = tid & 15;
    const float* Asrc = A + (size_t)(m0 + ra) * H_DIM + ha * 8;
    const float* Bsrc = Bg + (size_t)krb * H_DIM + col0 + csb * 8;

    float c[4][4][4];
    #pragma unroll
    for (int i = 0; i < 4; i++)
        #pragma unroll
        for (int j = 0; j < 4; j++)
            #pragma unroll
            for (int k = 0; k < 4; k++) c[i][j][k] = 0.f;

    const int NK = H_DIM / BKK;
    {
        unsigned da0 = smem_u32(&As[0][ra * AST + ha * 8]);
        cpa16(da0, Asrc, true); cpa16(da0 + 16, Asrc + 4, true);
        unsigned db0 = smem_u32(&Bs[0][krb * BST_KN + csb * 8]);
        cpa16(db0, Bsrc, true); cpa16(db0 + 16, Bsrc + 4, true);
        cpa_commit();
    }

    for (int it = 0; it < NK; it++) {
        if (it + 1 < NK) {
            int kk = (it + 1) * BKK, buf = (it + 1) & 1;
            unsigned da = smem_u32(&As[buf][ra * AST + ha * 8]);
            cpa16(da, Asrc + kk, true); cpa16(da + 16, Asrc + kk + 4, true);
            unsigned db = smem_u32(&Bs[buf][krb * BST_KN + csb * 8]);
            cpa16(db, Bsrc + (size_t)kk * H_DIM, true);
            cpa16(db + 16, Bsrc + (size_t)kk * H_DIM + 4, true);
        }
        cpa_commit();
        cpa_wait1();
        __syncthreads();

        const float* Ab = As[it & 1];
        const float* Bb = Bs[it & 1];
        int ar = lane >> 2, ak = lane & 3;
        #pragma unroll
        for (int kq = 0; kq < BKK; kq += 8) {
            unsigned af[4][4], bf[4][2];
            #pragma unroll
            for (int mt = 0; mt < 4; mt++) {
                int rb = wr * 64 + mt * 16;
                af[mt][0] = f2tf(Ab[(rb + ar)     * AST + kq + ak]);
                af[mt][1] = f2tf(Ab[(rb + ar + 8) * AST + kq + ak]);
                af[mt][2] = f2tf(Ab[(rb + ar)     * AST + kq + ak + 4]);
                af[mt][3] = f2tf(Ab[(rb + ar + 8) * AST + kq + ak + 4]);
            }
            #pragma unroll
            for (int nt = 0; nt < 4; nt++) {
                int cb = wc * 32 + nt * 8 + (lane >> 2);
                bf[nt][0] = f2tf(Bb[(kq + ak)     * BST_KN + cb]);
                bf[nt][1] = f2tf(Bb[(kq + ak + 4) * BST_KN + cb]);
            }
            #pragma unroll
            for (int mt = 0; mt < 4; mt++)
                #pragma unroll
                for (int nt = 0; nt < 4; nt++)
                    mma8(c[mt][nt], af[mt], bf[nt]);
        }
        __syncthreads();
    }

    #pragma unroll
    for (int mt = 0; mt < 4; mt++) {
        #pragma unroll
        for (int nt = 0; nt < 4; nt++) {
            int r0 = m0 + wr * 64 + mt * 16 + (lane >> 2);
            int cc = n0 + wc * 32 + nt * 8 + (lane & 3) * 2;
            float bv0 = bxl[g * H_DIM + (cc & 511)];
            float bv1 = bxl[g * H_DIM + ((cc + 1) & 511)];
            C[(size_t)r0 * 1536 + cc]           = c[mt][nt][0] + bv0;
            C[(size_t)r0 * 1536 + cc + 1]       = c[mt][nt][1] + bv1;
            C[(size_t)(r0 + 8) * 1536 + cc]     = c[mt][nt][2] + bv0;
            C[(size_t)(r0 + 8) * 1536 + cc + 1] = c[mt][nt][3] + bv1;
        }
    }
}

// ---------------- logits GEMM, 3-stage cp.async pipeline ------------------------
#define GBUF 2560
__global__ __launch_bounds__(256, 2)
void gemm_bt(const float* __restrict__ A,
             const float* __restrict__ Bm,
             const float* __restrict__ bias,
             float* __restrict__ C, int N) {
    extern __shared__ float sm[];
    float* AsB = sm;              // 3 * 2560
    float* BsB = sm + 3 * GBUF;   // 3 * 2560

    int tid = threadIdx.x;
    int lane = tid & 31, warp = tid >> 5;
    int wr = warp >> 2, wc = warp & 3;
    int m0 = blockIdx.y * BM, n0 = blockIdx.x * BN;

    const int ra = tid >> 1, ha = tid & 1;
    const int gn = n0 + ra;
    const bool bok = (gn < N);
    const float* Asrc = A + (size_t)(m0 + ra) * H_DIM + ha * 8;
    const float* Bsrc = Bm + (size_t)(bok ? gn : 0) * H_DIM + ha * 8;

    float c[4][4][4];
    #pragma unroll
    for (int i = 0; i < 4; i++)
        #pragma unroll
        for (int j = 0; j < 4; j++)
            #pragma unroll
            for (int k = 0; k < 4; k++) c[i][j][k] = 0.f;

    const int NK = H_DIM / BKK;   // 32
    #pragma unroll
    for (int s = 0; s < 2; s++) {
        int kk = s * BKK;
        unsigned da = smem_u32(&AsB[s * GBUF + ra * AST + ha * 8]);
        cpa16(da, Asrc + kk, true); cpa16(da + 16, Asrc + kk + 4, true);
        unsigned db = smem_u32(&BsB[s * GBUF + ra * BST_NK + ha * 8]);
        cpa16(db, Bsrc + kk, bok); cpa16(db + 16, Bsrc + kk + 4, bok);
        cpa_commit();
    }

    int buf = 0;
    for (int it = 0; it < NK; it++) {
        cpa_wait1();
        __syncthreads();

        const float* Ab = &AsB[buf * GBUF];
        const float* Bb = &BsB[buf * GBUF];
        int ar = lane >> 2, ak = lane & 3;
        #pragma unroll
        for (int kq = 0; kq < BKK; kq += 8) {
            unsigned af[4][4], bf[4][2];
            #pragma unroll
            for (int mt = 0; mt < 4; mt++) {
                int rb = wr * 64 + mt * 16;
                af[mt][0] = f2tf(Ab[(rb + ar)     * AST + kq + ak]);
                af[mt][1] = f2tf(Ab[(rb + ar + 8) * AST + kq + ak]);
                af[mt][2] = f2tf(Ab[(rb + ar)     * AST + kq + ak + 4]);
                af[mt][3] = f2tf(Ab[(rb + ar + 8) * AST + kq + ak + 4]);
            }
            #pragma unroll
            for (int nt = 0; nt < 4; nt++) {
                int cb = wc * 32 + nt * 8 + (lane >> 2);
                bf[nt][0] = f2tf(Bb[cb * BST_NK + kq + ak]);
                bf[nt][1] = f2tf(Bb[cb * BST_NK + kq + ak + 4]);
            }
            #pragma unroll
            for (int mt = 0; mt < 4; mt++)
                #pragma unroll
                for (int nt = 0; nt < 4; nt++)
                    mma8(c[mt][nt], af[mt], bf[nt]);
        }
        __syncthreads();

        if (it + 2 < NK) {
            int kk = (it + 2) * BKK;
            int nb = (it + 2) % 3;     // stage s lives in slot s%3
            unsigned da = smem_u32(&AsB[nb * GBUF + ra * AST + ha * 8]);
            cpa16(da, Asrc + kk, true); cpa16(da + 16, Asrc + kk + 4, true);
            unsigned db = smem_u32(&BsB[nb * GBUF + ra * BST_NK + ha * 8]);
            cpa16(db, Bsrc + kk, bok); cpa16(db + 16, Bsrc + kk + 4, bok);
        }
        cpa_commit();
        buf = (buf + 1) % 3;
    }

    #pragma unroll
    for (int mt = 0; mt < 4; mt++) {
        #pragma unroll
        for (int nt = 0; nt < 4; nt++) {
            int r0 = m0 + wr * 64 + mt * 16 + (lane >> 2);
            int cc = n0 + wc * 32 + nt * 8 + (lane & 3) * 2;
            if (cc < N) {
                float bv = bias[cc];
                C[(size_t)r0 * N + cc]       = c[mt][nt][0] + bv;
                C[(size_t)(r0 + 8) * N + cc] = c[mt][nt][2] + bv;
            }
            if (cc + 1 < N) {
                float bv = bias[cc + 1];
                C[(size_t)r0 * N + cc + 1]       = c[mt][nt][1] + bv;
                C[(size_t)(r0 + 8) * N + cc + 1] = c[mt][nt][3] + bv;
            }
        }
    }
}

// ---------------- persistent GRU recurrence: 8 clusters x 16 CTAs ----------------
// Cluster = sync domain = full k coverage: CTA rank owns outputs [rank*32, +32),
// cluster hg owns batches [hg*4, +4). Barriers are HW cluster barriers; h/rh
// exchanged via L2 (__stcg/__ldcg; barrier.cluster gives cluster-scope acq/rel).
#define HSS 516
__global__ __launch_bounds__(256)
void recur_kernel(const float* __restrict__ A, const float* __restrict__ U,
                  const float* __restrict__ h0, float* __restrict__ Y,
                  float* __restrict__ h_final) {
    extern __shared__ float smem[];
    float* Urz   = smem;                    // 64 rows x 516 (0-31: r cols, 32-63: z cols)
    float* Uc    = Urz + 64 * HSS;          // 32 rows x 516
    float* hS    = Uc + 32 * HSS;           // 4 b x 516
    float* zS    = hS + 4 * HSS;            // 128
    float* holdS = zS + 128;                // 128
    float* redS  = holdS + 128;             // 128

    const int tid = threadIdx.x;
    const int rank = blockIdx.x & 15, hg = blockIdx.x >> 4;
    const int o0 = rank * 32;

    // phase-1 roles: r1 = (gate,o_local) row 0..63, b1 = batch 0..3
    const int r1 = tid >> 2, b1 = tid & 3;
    const int gate = r1 >> 5, ol = r1 & 31;
    const int bg1 = hg * 4 + b1;
    // phase-2 roles: half = k half, r2 = o_local, b2 = batch
    const int half = tid >> 7, r2 = (tid >> 2) & 31, b2 = tid & 3;
    const int bg2 = hg * 4 + b2;

    // ---- stage transposed U (once): row-major [local_o][k], stride 516
    for (int idx = tid; idx < 4096; idx += 256) {
        int k = idx >> 3, o4 = idx & 7;
        float4 v0 = *(const float4*)(U + (size_t)k * H_DIM + o0 + o4 * 4);
        float4 v1 = *(const float4*)(U + (size_t)H_DIM * H_DIM + (size_t)k * H_DIM + o0 + o4 * 4);
        float4 v2 = *(const float4*)(U + 2 * (size_t)H_DIM * H_DIM + (size_t)k * H_DIM + o0 + o4 * 4);
        Urz[(o4 * 4 + 0) * HSS + k] = v0.x; Urz[(o4 * 4 + 1) * HSS + k] = v0.y;
        Urz[(o4 * 4 + 2) * HSS + k] = v0.z; Urz[(o4 * 4 + 3) * HSS + k] = v0.w;
        Urz[(32 + o4 * 4 + 0) * HSS + k] = v1.x; Urz[(32 + o4 * 4 + 1) * HSS + k] = v1.y;
        Urz[(32 + o4 * 4 + 2) * HSS + k] = v1.z; Urz[(32 + o4 * 4 + 3) * HSS + k] = v1.w;
        Uc[(o4 * 4 + 0) * HSS + k] = v2.x; Uc[(o4 * 4 + 1) * HSS + k] = v2.y;
        Uc[(o4 * 4 + 2) * HSS + k] = v2.z; Uc[(o4 * 4 + 3) * HSS + k] = v2.w;
    }

    // ---- seed g_h for this cluster's 4 batches (rank 0)
    if (rank == 0) {
        for (int i = tid; i < 512; i += 256) {
            int b = i >> 7, kq = i & 127;
            float4 v = *(const float4*)(h0 + (size_t)(hg * 4 + b) * H_DIM + kq * 4);
            __stcg((float4*)(g_h + (size_t)(hg * 4 + b) * H_DIM + kq * 4), v);
        }
    }
    cluster_sync();

    float hn_last = 0.f;

    for (int t = 0; t < S_LEN; ++t) {
        // prefetch A operands
        float av1 = __ldg(&A[(size_t)(t * B_SZ + bg1) * 1536 + gate * 512 + o0 + ol]);
        float av2 = (half == 0)
            ? __ldg(&A[(size_t)(t * B_SZ + bg2) * 1536 + 1024 + o0 + r2])
            : 0.f;

        // ---- stage h (4 batches x 512 k)
        for (int i = tid; i < 512; i += 256) {
            int b = i >> 7, kq = i & 127;
            float4 v = __ldcg((const float4*)(g_h + (size_t)(hg * 4 + b) * H_DIM + kq * 4));
            *(float4*)&hS[b * HSS + kq * 4] = v;
        }
        __syncthreads();

        // ---- phase 1: full-k dot for (gate, ol, b1); no reduction needed
        {
            const float* hb = hS + b1 * HSS;
            const float* ub = Urz + r1 * HSS;
            u64 a0 = 0ull, a1 = 0ull, a2 = 0ull, a3 = 0ull;
            #pragma unroll 8
            for (int c = 0; c < 128; c += 2) {
                ulonglong2 h0v = *(const ulonglong2*)(hb + c * 4);
                ulonglong2 u0v = *(const ulonglong2*)(ub + c * 4);
                ulonglong2 h1v = *(const ulonglong2*)(hb + c * 4 + 4);
                ulonglong2 u1v = *(const ulonglong2*)(ub + c * 4 + 4);
                fma2(a0, h0v.x, u0v.x); fma2(a1, h0v.y, u0v.y);
                fma2(a2, h1v.x, u1v.x); fma2(a3, h1v.y, u1v.y);
            }
            float sum = (acc_sum(a0) + acc_sum(a1)) + (acc_sum(a2) + acc_sum(a3)) + av1;
            float sg = 1.f / (1.f + __expf(-sum));
            if (gate == 0) {
                float hold = hS[b1 * HSS + o0 + ol];
                holdS[ol * 4 + b1] = hold;
                __stcg(&g_rh[(size_t)bg1 * H_DIM + o0 + ol], sg * hold);
            } else {
                zS[ol * 4 + b1] = sg;
            }
        }
        cluster_sync();

        // ---- stage rh
        for (int i = tid; i < 512; i += 256) {
            int b = i >> 7, kq = i & 127;
            float4 v = __ldcg((const float4*)(g_rh + (size_t)(hg * 4 + b) * H_DIM + kq * 4));
            *(float4*)&hS[b * HSS + kq * 4] = v;
        }
        __syncthreads();

        // ---- phase 2: k-half dot for (r2, b2)
        float partial;
        {
            const float* hb = hS + b2 * HSS + half * 256;
            const float* ub = Uc + r2 * HSS + half * 256;
            u64 a0 = 0ull, a1 = 0ull;
            #pragma unroll 8
            for (int c = 0; c < 64; c++) {
                ulonglong2 hv = *(const ulonglong2*)(hb + c * 4);
                ulonglong2 uv = *(const ulonglong2*)(ub + c * 4);
                fma2(a0, hv.x, uv.x); fma2(a1, hv.y, uv.y);
            }
            partial = acc_sum(a0) + acc_sum(a1);
            if (half) redS[r2 * 4 + b2] = partial;
        }
        __syncthreads();

        // ---- phase 2 finalize (half 0 threads)
        if (half == 0) {
            float total = partial + redS[r2 * 4 + b2] + av2;
            float hh = tanhf(total);
            float z = zS[r2 * 4 + b2];
            float hold = holdS[r2 * 4 + b2];
            float hn = fmaf(z, hh - hold, hold);
            hn_last = hn;
            __stcg(&g_h[(size_t)bg2 * H_DIM + o0 + r2], hn);
            __stcg(&Y[(size_t)(t * B_SZ + bg2) * H_DIM + o0 + r2], hn);
        }
        cluster_sync();
    }

    if (half == 0)
        h_final[(size_t)bg2 * H_DIM + o0 + r2] = hn_last;
}

// ---------------- launch ----------------
extern "C" void kernel_launch(void* const* d_in, const int* in_sizes, int n_in,
                              void* d_out, int out_size) {
    const void*  tokens = d_in[0];
    const float* h0  = (const float*)d_in[1];
    const float* emb = (const float*)d_in[2];
    const float* Wx  = (const float*)d_in[3];
    const float* bx  = (const float*)d_in[4];
    const float* U   = (const float*)d_in[5];
    const float* Wy  = (const float*)d_in[6];
    const float* by  = (const float*)d_in[7];

    float* logits = (float*)d_out;                              // [S,B,V]
    float* hfin   = logits + (size_t)S_LEN * B_SZ * V_SZ;       // [L,B,H]

    float *dX, *dY, *dA;
    cudaGetSymbolAddress((void**)&dX, g_X);
    cudaGetSymbolAddress((void**)&dY, g_Y);
    cudaGetSymbolAddress((void**)&dA, g_A);

    const int M = S_LEN * B_SZ;
    const int RSMEM = (64 * HSS + 32 * HSS + 4 * HSS + 384) * 4;   // 207936
    cudaFuncSetAttribute(recur_kernel, cudaFuncAttributeMaxDynamicSharedMemorySize, RSMEM);
    cudaFuncSetAttribute(recur_kernel, cudaFuncAttributeNonPortableClusterSizeAllowed, 1);
    const int GSMEM = 6 * GBUF * 4;   // 61440
    cudaFuncSetAttribute(gemm_bt, cudaFuncAttributeMaxDynamicSharedMemorySize, GSMEM);

    dim3 blk(256);

    detect_kernel<<<1, 32>>>((const int*)tokens);
    embed_kernel<<<M, 128>>>(tokens, emb, dX);

    gemm_ax<<<dim3(12, M / 128), blk>>>(dX, Wx, bx, dA);

    // cluster launch config for the recurrence (8 clusters x 16 CTAs)
    cudaLaunchConfig_t cfg = {};
    cfg.gridDim = dim3(128, 1, 1);
    cfg.blockDim = dim3(256, 1, 1);
    cfg.dynamicSmemBytes = RSMEM;
    cfg.stream = 0;
    cudaLaunchAttribute attrs[1];
    attrs[0].id = cudaLaunchAttributeClusterDimension;
    attrs[0].val.clusterDim.x = 16;
    attrs[0].val.clusterDim.y = 1;
    attrs[0].val.clusterDim.z = 1;
    cfg.attrs = attrs;
    cfg.numAttrs = 1;

    cudaLaunchKernelEx(&cfg, recur_kernel, (const float*)dA, U, h0,
                       (float*)dY, (float*)hfin);

    gemm_ax<<<dim3(12, M / 128), blk>>>(dY, Wx + (size_t)3 * H_DIM * H_DIM,
                                        bx + 3 * H_DIM, dA);

    cudaLaunchKernelEx(&cfg, recur_kernel, (const float*)dA,
                       U + (size_t)3 * H_DIM * H_DIM, h0 + B_SZ * H_DIM,
                       (float*)dX, (float*)(hfin + B_SZ * H_DIM));

    gemm_bt<<<dim3((V_SZ + 127) / 128, M / 128), blk, GSMEM>>>(dX, Wy, by, logits, V_SZ);
}

// round 11
// speedup vs baseline: 1.6958x; 1.4741x over previous
#include <cuda_runtime.h>
#include <cstdint>

#define S_LEN 128
#define B_SZ  32
#define H_DIM 512
#define V_SZ  10000

typedef unsigned long long u64;

// ---------------- scratch (device globals; no allocation allowed) ----------------
__device__ float g_X[S_LEN * B_SZ * H_DIM];       // layer input / tops (8 MB)
__device__ float g_A[S_LEN * B_SZ * 3 * H_DIM];   // precomputed x@Wx0+bx0 (24 MB)
__device__ float g_h0[B_SZ * H_DIM];              // layer-0 h
__device__ float g_h1[B_SZ * H_DIM];              // layer-1 h
__device__ float g_rh0[B_SZ * H_DIM];             // layer-0 r*h
__device__ float g_rh1[B_SZ * H_DIM];             // layer-1 r*h
__device__ int   g_is64;

// ---------------- per-domain grid barrier (2 domains x 64 CTAs) ------------------
__device__ unsigned          g_cnt2[2 * 32];
__device__ volatile unsigned g_gen2[2 * 32];

__device__ __forceinline__ void bg_barrier(int bg) {
    __syncthreads();
    if (threadIdx.x == 0) {
        volatile unsigned* genp = &g_gen2[bg * 32];
        unsigned* cntp = &g_cnt2[bg * 32];
        unsigned gen = *genp;
        __threadfence();
        if (atomicAdd(cntp, 1u) == 63u) {
            *cntp = 0;
            __threadfence();
            *genp = gen + 1;
        } else {
            unsigned it = 0;
            while (*genp == gen) {
                if (++it > 65536u) { __nanosleep(32); }
                if (it > 400000u) break;   // safety valve: never hang
            }
        }
        __threadfence();
    }
    __syncthreads();
}

// ---------------- token dtype detector ----------------
__global__ void detect_kernel(const int* __restrict__ t32) {
    if (threadIdx.x == 0 && blockIdx.x == 0) {
        unsigned o = 0;
        for (int i = 0; i < 128; i++) o |= (unsigned)t32[2 * i + 1];
        g_is64 = (o == 0) ? 1 : 0;
    }
}

// ---------------- embedding gather (dtype-robust, clamped) ----------------
__global__ void embed_kernel(const void* __restrict__ tok,
                             const float* __restrict__ emb,
                             float* __restrict__ X) {
    int row = blockIdx.x;
    long long t;
    if (g_is64) t = ((const long long*)tok)[row];
    else        t = (long long)((const int*)tok)[row];
    if (t < 0) t = 0;
    if (t >= V_SZ) t = V_SZ - 1;
    const float4* src = (const float4*)(emb + (size_t)t * H_DIM);
    float4* dst = (float4*)(X + (size_t)row * H_DIM);
    for (int i = threadIdx.x; i < H_DIM / 4; i += blockDim.x) dst[i] = src[i];
}

// ---------------- tf32 mma + cp.async helpers ----------------
#define BM 128
#define BN 128
#define BKK 16
#define AST 20
#define BST_KN 136
#define BST_NK 20

__device__ __forceinline__ unsigned f2tf(float x) {
    unsigned r; asm("cvt.rna.tf32.f32 %0, %1;" : "=r"(r) : "f"(x)); return r;
}
__device__ __forceinline__ void mma8(float* c, const unsigned* a, const unsigned* b) {
    asm volatile(
        "mma.sync.aligned.m16n8k8.row.col.f32.tf32.tf32.f32 "
        "{%0,%1,%2,%3}, {%4,%5,%6,%7}, {%8,%9}, {%0,%1,%2,%3};\n"
        : "+f"(c[0]), "+f"(c[1]), "+f"(c[2]), "+f"(c[3])
        : "r"(a[0]), "r"(a[1]), "r"(a[2]), "r"(a[3]), "r"(b[0]), "r"(b[1]));
}
__device__ __forceinline__ void cpa16(unsigned dst, const void* src, bool pred) {
    int sz = pred ? 16 : 0;
    asm volatile("cp.async.cg.shared.global [%0], [%1], 16, %2;\n"
                 :: "r"(dst), "l"(src), "r"(sz));
}
__device__ __forceinline__ void cpa_commit() {
    asm volatile("cp.async.commit_group;\n" ::: "memory");
}
__device__ __forceinline__ void cpa_wait1() {
    asm volatile("cp.async.wait_group 1;\n" ::: "memory");
}
__device__ __forceinline__ unsigned smem_u32(const void* p) {
    return (unsigned)__cvta_generic_to_shared(p);
}
__device__ __forceinline__ void fma2(u64& acc, u64 a, u64 b) {
    asm("fma.rn.f32x2 %0, %1, %2, %0;" : "+l"(acc) : "l"(a), "l"(b));
}
__device__ __forceinline__ float acc_sum(u64 a) {
    unsigned lo, hi;
    asm("mov.b64 {%0,%1}, %2;" : "=r"(lo), "=r"(hi) : "l"(a));
    return __uint_as_float(lo) + __uint_as_float(hi);
}

// ---------- fused 3-gate input GEMM for layer 0 (2-stage cp.async) --------------
__global__ __launch_bounds__(256, 2)
void gemm_ax(const float* __restrict__ A,          // X [M,512]
             const float* __restrict__ Wxl,        // [3,512,512]
             const float* __restrict__ bxl,        // [3,512]
             float* __restrict__ C) {              // [M,1536]
    __shared__ float As[2][BM * AST];
    __shared__ float Bs[2][BKK * BST_KN];

    int tid = threadIdx.x;
    int lane = tid & 31, warp = tid >> 5;
    int wr = warp >> 2, wc = warp & 3;
    int m0 = blockIdx.y * BM, n0 = blockIdx.x * BN;
    int g = n0 >> 9, col0 = n0 & 511;
    const float* Bg = Wxl + (size_t)g * H_DIM * H_DIM;

    const int ra = tid >> 1, ha = tid & 1;
    const int krb = tid >> 4, csb = tid & 15;
    const float* Asrc = A + (size_t)(m0 + ra) * H_DIM + ha * 8;
    const float* Bsrc = Bg + (size_t)krb * H_DIM + col0 + csb * 8;

    float c[4][4][4];
    #pragma unroll
    for (int i = 0; i < 4; i++)
        #pragma unroll
        for (int j = 0; j < 4; j++)
            #pragma unroll
            for (int k = 0; k < 4; k++) c[i][j][k] = 0.f;

    const int NK = H_DIM / BKK;
    {
        unsigned da0 = smem_u32(&As[0][ra * AST + ha * 8]);
        cpa16(da0, Asrc, true); cpa16(da0 + 16, Asrc + 4, true);
        unsigned db0 = smem_u32(&Bs[0][krb * BST_KN + csb * 8]);
        cpa16(db0, Bsrc, true); cpa16(db0 + 16, Bsrc + 4, true);
        cpa_commit();
    }

    for (int it = 0; it < NK; it++) {
        if (it + 1 < NK) {
            int kk = (it + 1) * BKK, buf = (it + 1) & 1;
            unsigned da = smem_u32(&As[buf][ra * AST + ha * 8]);
            cpa16(da, Asrc + kk, true); cpa16(da + 16, Asrc + kk + 4, true);
            unsigned db = smem_u32(&Bs[buf][krb * BST_KN + csb * 8]);
            cpa16(db, Bsrc + (size_t)kk * H_DIM, true);
            cpa16(db + 16, Bsrc + (size_t)kk * H_DIM + 4, true);
        }
        cpa_commit();
        cpa_wait1();
        __syncthreads();

        const float* Ab = As[it & 1];
        const float* Bb = Bs[it & 1];
        int ar = lane >> 2, ak = lane & 3;
        #pragma unroll
        for (int kq = 0; kq < BKK; kq += 8) {
            unsigned af[4][4], bf[4][2];
            #pragma unroll
            for (int mt = 0; mt < 4; mt++) {
                int rb = wr * 64 + mt * 16;
                af[mt][0] = f2tf(Ab[(rb + ar)     * AST + kq + ak]);
                af[mt][1] = f2tf(Ab[(rb + ar + 8) * AST + kq + ak]);
                af[mt][2] = f2tf(Ab[(rb + ar)     * AST + kq + ak + 4]);
                af[mt][3] = f2tf(Ab[(rb + ar + 8) * AST + kq + ak + 4]);
            }
            #pragma unroll
            for (int nt = 0; nt < 4; nt++) {
                int cb = wc * 32 + nt * 8 + (lane >> 2);
                bf[nt][0] = f2tf(Bb[(kq + ak)     * BST_KN + cb]);
                bf[nt][1] = f2tf(Bb[(kq + ak + 4) * BST_KN + cb]);
            }
            #pragma unroll
            for (int mt = 0; mt < 4; mt++)
                #pragma unroll
                for (int nt = 0; nt < 4; nt++)
                    mma8(c[mt][nt], af[mt], bf[nt]);
        }
        __syncthreads();
    }

    #pragma unroll
    for (int mt = 0; mt < 4; mt++) {
        #pragma unroll
        for (int nt = 0; nt < 4; nt++) {
            int r0 = m0 + wr * 64 + mt * 16 + (lane >> 2);
            int cc = n0 + wc * 32 + nt * 8 + (lane & 3) * 2;
            float bv0 = bxl[g * H_DIM + (cc & 511)];
            float bv1 = bxl[g * H_DIM + ((cc + 1) & 511)];
            C[(size_t)r0 * 1536 + cc]           = c[mt][nt][0] + bv0;
            C[(size_t)r0 * 1536 + cc + 1]       = c[mt][nt][1] + bv1;
            C[(size_t)(r0 + 8) * 1536 + cc]     = c[mt][nt][2] + bv0;
            C[(size_t)(r0 + 8) * 1536 + cc + 1] = c[mt][nt][3] + bv1;
        }
    }
}

// ---------------- logits GEMM, 3-stage cp.async pipeline ------------------------
#define GBUF 2560
__global__ __launch_bounds__(256, 2)
void gemm_bt(const float* __restrict__ A,
             const float* __restrict__ Bm,
             const float* __restrict__ bias,
             float* __restrict__ C, int N) {
    extern __shared__ float sm[];
    float* AsB = sm;
    float* BsB = sm + 3 * GBUF;

    int tid = threadIdx.x;
    int lane = tid & 31, warp = tid >> 5;
    int wr = warp >> 2, wc = warp & 3;
    int m0 = blockIdx.y * BM, n0 = blockIdx.x * BN;

    const int ra = tid >> 1, ha = tid & 1;
    const int gn = n0 + ra;
    const bool bok = (gn < N);
    const float* Asrc = A + (size_t)(m0 + ra) * H_DIM + ha * 8;
    const float* Bsrc = Bm + (size_t)(bok ? gn : 0) * H_DIM + ha * 8;

    float c[4][4][4];
    #pragma unroll
    for (int i = 0; i < 4; i++)
        #pragma unroll
        for (int j = 0; j < 4; j++)
            #pragma unroll
            for (int k = 0; k < 4; k++) c[i][j][k] = 0.f;

    const int NK = H_DIM / BKK;
    #pragma unroll
    for (int s = 0; s < 2; s++) {
        int kk = s * BKK;
        unsigned da = smem_u32(&AsB[s * GBUF + ra * AST + ha * 8]);
        cpa16(da, Asrc + kk, true); cpa16(da + 16, Asrc + kk + 4, true);
        unsigned db = smem_u32(&BsB[s * GBUF + ra * BST_NK + ha * 8]);
        cpa16(db, Bsrc + kk, bok); cpa16(db + 16, Bsrc + kk + 4, bok);
        cpa_commit();
    }

    int buf = 0;
    for (int it = 0; it < NK; it++) {
        cpa_wait1();
        __syncthreads();

        const float* Ab = &AsB[buf * GBUF];
        const float* Bb = &BsB[buf * GBUF];
        int ar = lane >> 2, ak = lane & 3;
        #pragma unroll
        for (int kq = 0; kq < BKK; kq += 8) {
            unsigned af[4][4], bf[4][2];
            #pragma unroll
            for (int mt = 0; mt < 4; mt++) {
                int rb = wr * 64 + mt * 16;
                af[mt][0] = f2tf(Ab[(rb + ar)     * AST + kq + ak]);
                af[mt][1] = f2tf(Ab[(rb + ar + 8) * AST + kq + ak]);
                af[mt][2] = f2tf(Ab[(rb + ar)     * AST + kq + ak + 4]);
                af[mt][3] = f2tf(Ab[(rb + ar + 8) * AST + kq + ak + 4]);
            }
            #pragma unroll
            for (int nt = 0; nt < 4; nt++) {
                int cb = wc * 32 + nt * 8 + (lane >> 2);
                bf[nt][0] = f2tf(Bb[cb * BST_NK + kq + ak]);
                bf[nt][1] = f2tf(Bb[cb * BST_NK + kq + ak + 4]);
            }
            #pragma unroll
            for (int mt = 0; mt < 4; mt++)
                #pragma unroll
                for (int nt = 0; nt < 4; nt++)
                    mma8(c[mt][nt], af[mt], bf[nt]);
        }
        __syncthreads();

        if (it + 2 < NK) {
            int kk = (it + 2) * BKK;
            int nb = (it + 2) % 3;
            unsigned da = smem_u32(&AsB[nb * GBUF + ra * AST + ha * 8]);
            cpa16(da, Asrc + kk, true); cpa16(da + 16, Asrc + kk + 4, true);
            unsigned db = smem_u32(&BsB[nb * GBUF + ra * BST_NK + ha * 8]);
            cpa16(db, Bsrc + kk, bok); cpa16(db + 16, Bsrc + kk + 4, bok);
        }
        cpa_commit();
        buf = (buf + 1) % 3;
    }

    #pragma unroll
    for (int mt = 0; mt < 4; mt++) {
        #pragma unroll
        for (int nt = 0; nt < 4; nt++) {
            int r0 = m0 + wr * 64 + mt * 16 + (lane >> 2);
            int cc = n0 + wc * 32 + nt * 8 + (lane & 3) * 2;
            if (cc < N) {
                float bv = bias[cc];
                C[(size_t)r0 * N + cc]       = c[mt][nt][0] + bv;
                C[(size_t)(r0 + 8) * N + cc] = c[mt][nt][2] + bv;
            }
            if (cc + 1 < N) {
                float bv = bias[cc + 1];
                C[(size_t)r0 * N + cc + 1]       = c[mt][nt][1] + bv;
                C[(size_t)(r0 + 8) * N + cc + 1] = c[mt][nt][3] + bv;
            }
        }
    }
}

// ========== fused two-layer pipelined GRU recurrence (128 CTAs, persistent) =====
// CTA = (bg 0..1, og 0..63): 8 outputs x 16 batches, BOTH layers.
// vt = 0..128: layer-0 does step vt (vt<128), layer-1 does step vt-1 (vt>0).
// Layer-1 input projection folded as concat dot [y0; h1] . [Wx1col; U1col].
#define HST 1028          // hS / W1 row stride (floats)
#define W0ST 516          // W0 row stride
__global__ __launch_bounds__(256)
void recur_fused(const float* __restrict__ A,     // layer-0 ax [S,32,1536]
                 const float* __restrict__ U,     // [2,3,512,512]
                 const float* __restrict__ Wx,    // [2,3,512,512]
                 const float* __restrict__ bx,    // [2,3,512]
                 const float* __restrict__ h0in,  // [2,32,512]
                 float* __restrict__ Y,           // tops [S,32,512]
                 float* __restrict__ hfin) {      // [2,32,512]
    extern __shared__ float smem[];
    float* W0    = smem;                          // 24 x 516  (r,z,c gates x 8 o)
    float* W1    = W0 + 24 * W0ST;                // 24 x 1028 (concat Wx1|U1)
    float* hS    = W1 + 24 * HST;                 // 16 b x 1028: [h0prev | h1prev/rh]
    float* redS  = hS + 16 * HST;                 // 32 x 34 (p1) / 8 x 68 (p2)
    float* zS    = redS + 32 * 34;                // 16 x 17 (L*8+ol)
    float* holdS = zS + 16 * 17;                  // 16 x 17

    const int tid = threadIdx.x, lane = tid & 31, w = tid >> 5;
    const int og = blockIdx.x & 63, bg = blockIdx.x >> 6;
    const int o0 = og * 8;

    // p1 compute roles
    const int q = w & 1, rg = w >> 1;             // rg: 0 L0r 1 L0z 2 L1r 3 L1z
    const int gr = rg & 1;
    const int bl = lane & 15, slot = lane >> 4;   // 16 batches x 2 row-slots
    // p1/p2 finalize roles
    const int frow = tid >> 4, fb = tid & 15;     // frow 0..15, fb 0..15
    const int fo = o0 + (frow & 7);
    const int fbglob = bg * 16 + fb;
    // p2 compute roles
    const int q2 = w & 3, sh = w >> 2;            // k-quarter x row-half

    // ---- stage weights (once) ----
    // W0: rows (g*8+ol) = U0[g][k][o0+ol]
    for (int idx = tid; idx < 12288; idx += 256) {
        int g = idx >> 12, r = idx & 4095, k = r >> 3, ol = r & 7;
        W0[(g * 8 + ol) * W0ST + k] =
            U[(size_t)g * 262144 + (size_t)k * 512 + o0 + ol];
    }
    // W1: rows (g*8+ol): [Wx1[g][k][o] (k<512) | U1[g][k-512][o]]
    for (int idx = tid; idx < 24576; idx += 256) {
        int g = idx >> 13, r = idx & 8191, k = r >> 3, ol = r & 7;
        float v;
        if (k < 512) v = Wx[(size_t)(3 + g) * 262144 + (size_t)k * 512 + o0 + ol];
        else         v = U[(size_t)(3 + g) * 262144 + (size_t)(k - 512) * 512 + o0 + ol];
        W1[(g * 8 + ol) * HST + k] = v;
    }

    // constant bias loads (layer 1)
    float av1b = __ldg(&bx[(size_t)(3 + (frow >> 3)) * 512 + fo]);   // p1 L1 gate bias
    float av2b = (tid < 128) ? __ldg(&bx[(size_t)5 * 512 + o0 + (tid >> 4)]) : 0.f;

    // ---- seed h states (og==0 CTA per bg) ----
    if (og == 0) {
        for (int i = tid; i < 2048; i += 256) {
            int b = i >> 7, f = i & 127;
            float4 v0 = *(const float4*)(h0in + (size_t)(bg * 16 + b) * 512 + f * 4);
            float4 v1 = *(const float4*)(h0in + 16384 + (size_t)(bg * 16 + b) * 512 + f * 4);
            __stcg((float4*)(g_h0 + (size_t)(bg * 16 + b) * 512 + f * 4), v0);
            __stcg((float4*)(g_h1 + (size_t)(bg * 16 + b) * 512 + f * 4), v1);
        }
    }
    bg_barrier(bg);

    for (int vt = 0; vt <= S_LEN; ++vt) {
        const bool l0 = (vt < S_LEN);
        const bool l1 = (vt > 0);
        const int t1 = vt - 1;

        // prefetch layer-0 A operands for finalize roles
        float av1a = 0.f, av2a = 0.f;
        if (l0) {
            av1a = __ldg(&A[((size_t)vt * 32 + fbglob) * 1536 + (frow >> 3) * 512 + fo]);
            if (tid < 128)
                av2a = __ldg(&A[((size_t)vt * 32 + fbglob) * 1536 + 1024 + o0 + (tid >> 4)]);
        }

        // ---- stage h0prev and h1prev ----
        for (int i = tid; i < 2048; i += 256) {
            int b = i >> 7, f = i & 127;
            *(float4*)&hS[b * HST + f * 4] =
                __ldcg((const float4*)(g_h0 + (size_t)(bg * 16 + b) * 512 + f * 4));
        }
        for (int i = tid; i < 2048; i += 256) {
            int b = i >> 7, f = i & 127;
            *(float4*)&hS[b * HST + 512 + f * 4] =
                __ldcg((const float4*)(g_h1 + (size_t)(bg * 16 + b) * 512 + f * 4));
        }
        __syncthreads();

        // ---- phase 1 compute ----
        if (rg < 2) {
            if (l0) {
                const float* hp = hS + bl * HST + q * 256;
                const float* up = W0 + (gr * 8 + slot * 4) * W0ST + q * 256;
                u64 a0 = 0ull, a1 = 0ull, a2 = 0ull, a3 = 0ull;
                #pragma unroll 4
                for (int c = 0; c < 64; c++) {
                    ulonglong2 hv = *(const ulonglong2*)(hp + c * 4);
                    ulonglong2 u0 = *(const ulonglong2*)(up + c * 4);
                    ulonglong2 u1 = *(const ulonglong2*)(up + W0ST + c * 4);
                    ulonglong2 u2 = *(const ulonglong2*)(up + 2 * W0ST + c * 4);
                    ulonglong2 u3 = *(const ulonglong2*)(up + 3 * W0ST + c * 4);
                    fma2(a0, hv.x, u0.x); fma2(a1, hv.x, u1.x);
                    fma2(a2, hv.x, u2.x); fma2(a3, hv.x, u3.x);
                    fma2(a0, hv.y, u0.y); fma2(a1, hv.y, u1.y);
                    fma2(a2, hv.y, u2.y); fma2(a3, hv.y, u3.y);
                }
                int row = rg * 8 + slot * 4;
                redS[(row + 0) * 34 + bl * 2 + q] = acc_sum(a0);
                redS[(row + 1) * 34 + bl * 2 + q] = acc_sum(a1);
                redS[(row + 2) * 34 + bl * 2 + q] = acc_sum(a2);
                redS[(row + 3) * 34 + bl * 2 + q] = acc_sum(a3);
            }
        } else {
            if (l1) {
                const float* hp = hS + bl * HST + q * 512;
                const float* up = W1 + (gr * 8 + slot * 4) * HST + q * 512;
                u64 a0 = 0ull, a1 = 0ull, a2 = 0ull, a3 = 0ull;
                #pragma unroll 4
                for (int c = 0; c < 128; c++) {
                    ulonglong2 hv = *(const ulonglong2*)(hp + c * 4);
                    ulonglong2 u0 = *(const ulonglong2*)(up + c * 4);
                    ulonglong2 u1 = *(const ulonglong2*)(up + HST + c * 4);
                    ulonglong2 u2 = *(const ulonglong2*)(up + 2 * HST + c * 4);
                    ulonglong2 u3 = *(const ulonglong2*)(up + 3 * HST + c * 4);
                    fma2(a0, hv.x, u0.x); fma2(a1, hv.x, u1.x);
                    fma2(a2, hv.x, u2.x); fma2(a3, hv.x, u3.x);
                    fma2(a0, hv.y, u0.y); fma2(a1, hv.y, u1.y);
                    fma2(a2, hv.y, u2.y); fma2(a3, hv.y, u3.y);
                }
                int row = rg * 8 + slot * 4;
                redS[(row + 0) * 34 + bl * 2 + q] = acc_sum(a0);
                redS[(row + 1) * 34 + bl * 2 + q] = acc_sum(a1);
                redS[(row + 2) * 34 + bl * 2 + q] = acc_sum(a2);
                redS[(row + 3) * 34 + bl * 2 + q] = acc_sum(a3);
            }
        }
        __syncthreads();

        // ---- phase 1 finalize: task0 = L0 row frow, task1 = L1 row frow ----
        if (l0) {
            float s = redS[frow * 34 + fb * 2] + redS[frow * 34 + fb * 2 + 1] + av1a;
            float sg = 1.f / (1.f + __expf(-s));
            if (frow < 8) {
                float hold = hS[fb * HST + fo];
                holdS[frow * 17 + fb] = hold;
                __stcg(&g_rh0[(size_t)fbglob * 512 + fo], sg * hold);
            } else {
                zS[(frow - 8) * 17 + fb] = sg;
            }
        }
        if (l1) {
            int row1 = 16 + frow;
            float s = redS[row1 * 34 + fb * 2] + redS[row1 * 34 + fb * 2 + 1] + av1b;
            float sg = 1.f / (1.f + __expf(-s));
            if (frow < 8) {
                float hold = hS[fb * HST + 512 + fo];
                holdS[(8 + frow) * 17 + fb] = hold;
                __stcg(&g_rh1[(size_t)fbglob * 512 + fo], sg * hold);
            } else {
                zS[(8 + frow - 8) * 17 + fb] = sg;
            }
        }
        bg_barrier(bg);

        // ---- stage rh0 into second slot ----
        if (l0) {
            for (int i = tid; i < 2048; i += 256) {
                int b = i >> 7, f = i & 127;
                *(float4*)&hS[b * HST + 512 + f * 4] =
                    __ldcg((const float4*)(g_rh0 + (size_t)(bg * 16 + b) * 512 + f * 4));
            }
        }
        __syncthreads();

        // ---- phase 2 L0 compute: candidate over rh0 ----
        if (l0) {
            #pragma unroll
            for (int j = 0; j < 2; j++) {
                int ol = sh * 4 + slot * 2 + j;
                const float* hp = hS + bl * HST + 512 + q2 * 128;
                const float* up = W0 + (16 + ol) * W0ST + q2 * 128;
                u64 a0 = 0ull, a1 = 0ull;
                #pragma unroll 4
                for (int c = 0; c < 32; c++) {
                    ulonglong2 hv = *(const ulonglong2*)(hp + c * 4);
                    ulonglong2 uv = *(const ulonglong2*)(up + c * 4);
                    fma2(a0, hv.x, uv.x); fma2(a1, hv.y, uv.y);
                }
                redS[ol * 68 + bl * 4 + q2] = acc_sum(a0) + acc_sum(a1);
            }
        }
        __syncthreads();

        // ---- phase 2 L0 finalize + restage rh1 ----
        if (l0 && tid < 128) {
            int row = tid >> 4;
            float4 p = *(const float4*)&redS[row * 68 + fb * 4];
            float hh = tanhf((p.x + p.y) + (p.z + p.w) + av2a);
            float z = zS[row * 17 + fb];
            float hold = holdS[row * 17 + fb];
            float hn = fmaf(z, hh - hold, hold);
            __stcg(&g_h0[(size_t)fbglob * 512 + o0 + row], hn);
        }
        if (l1) {
            for (int i = tid; i < 2048; i += 256) {
                int b = i >> 7, f = i & 127;
                *(float4*)&hS[b * HST + 512 + f * 4] =
                    __ldcg((const float4*)(g_rh1 + (size_t)(bg * 16 + b) * 512 + f * 4));
            }
        }
        __syncthreads();

        // ---- phase 2 L1 compute: concat [h0prev | rh1], k-quarters of 1024 ----
        if (l1) {
            #pragma unroll
            for (int j = 0; j < 2; j++) {
                int ol = sh * 4 + slot * 2 + j;
                const float* hp = (q2 < 2) ? (hS + bl * HST + q2 * 256)
                                           : (hS + bl * HST + 512 + (q2 - 2) * 256);
                const float* up = W1 + (16 + ol) * HST + q2 * 256;
                u64 a0 = 0ull, a1 = 0ull;
                #pragma unroll 4
                for (int c = 0; c < 64; c++) {
                    ulonglong2 hv = *(const ulonglong2*)(hp + c * 4);
                    ulonglong2 uv = *(const ulonglong2*)(up + c * 4);
                    fma2(a0, hv.x, uv.x); fma2(a1, hv.y, uv.y);
                }
                redS[ol * 68 + bl * 4 + q2] = acc_sum(a0) + acc_sum(a1);
            }
        }
        __syncthreads();

        // ---- phase 2 L1 finalize: h1 update + tops output ----
        if (l1 && tid < 128) {
            int row = tid >> 4;
            float4 p = *(const float4*)&redS[row * 68 + fb * 4];
            float hh = tanhf((p.x + p.y) + (p.z + p.w) + av2b);
            float z = zS[(8 + row) * 17 + fb];
            float hold = holdS[(8 + row) * 17 + fb];
            float hn = fmaf(z, hh - hold, hold);
            __stcg(&g_h1[(size_t)fbglob * 512 + o0 + row], hn);
            __stcg(&Y[((size_t)t1 * 32 + fbglob) * 512 + o0 + row], hn);
        }
        bg_barrier(bg);
    }

    // ---- final hidden states ----
    if (og == 0) {
        for (int i = tid; i < 2048; i += 256) {
            int b = i >> 7, f = i & 127;
            float4 v0 = __ldcg((const float4*)(g_h0 + (size_t)(bg * 16 + b) * 512 + f * 4));
            float4 v1 = __ldcg((const float4*)(g_h1 + (size_t)(bg * 16 + b) * 512 + f * 4));
            *(float4*)(hfin + (size_t)(bg * 16 + b) * 512 + f * 4) = v0;
            *(float4*)(hfin + 16384 + (size_t)(bg * 16 + b) * 512 + f * 4) = v1;
        }
    }
}

// ---------------- launch ----------------
extern "C" void kernel_launch(void* const* d_in, const int* in_sizes, int n_in,
                              void* d_out, int out_size) {
    const void*  tokens = d_in[0];
    const float* h0  = (const float*)d_in[1];
    const float* emb = (const float*)d_in[2];
    const float* Wx  = (const float*)d_in[3];
    const float* bx  = (const float*)d_in[4];
    const float* U   = (const float*)d_in[5];
    const float* Wy  = (const float*)d_in[6];
    const float* by  = (const float*)d_in[7];

    float* logits = (float*)d_out;                              // [S,B,V]
    float* hfin   = logits + (size_t)S_LEN * B_SZ * V_SZ;       // [L,B,H]

    float *dX, *dA;
    cudaGetSymbolAddress((void**)&dX, g_X);
    cudaGetSymbolAddress((void**)&dA, g_A);

    const int M = S_LEN * B_SZ;
    const int RSMEM = (24 * W0ST + 24 * HST + 16 * HST + 32 * 34 + 2 * 16 * 17) * 4;
    cudaFuncSetAttribute(recur_fused, cudaFuncAttributeMaxDynamicSharedMemorySize, RSMEM);
    const int GSMEM = 6 * GBUF * 4;
    cudaFuncSetAttribute(gemm_bt, cudaFuncAttributeMaxDynamicSharedMemorySize, GSMEM);

    dim3 blk(256);

    detect_kernel<<<1, 32>>>((const int*)tokens);
    embed_kernel<<<M, 128>>>(tokens, emb, dX);

    // A0 = X @ Wx[0] + bx[0] (layer 0 only)
    gemm_ax<<<dim3(12, M / 128), blk>>>(dX, Wx, bx, dA);

    // fused two-layer pipelined recurrence -> tops into dX, finals into hfin
    recur_fused<<<128, 256, RSMEM>>>(dA, U, Wx, bx, h0, dX, hfin);

    // logits = tops @ Wy^T + by
    gemm_bt<<<dim3((V_SZ + 127) / 128, M / 128), blk, GSMEM>>>(dX, Wy, by, logits, V_SZ);
}